// round 16
// baseline (speedup 1.0000x reference)
#include <cuda_runtime.h>
#include <cuda_fp16.h>
#include <cstdint>
#include <cstddef>

using f16 = __half;

constexpr int kB  = 2;
constexpr int kS  = 2048;
constexpr int kH  = 2048;
constexpr int kNH = 16;
constexpr int kHD = 128;
constexpr int kM  = kB * kS;   // 4096

// ------------- projection GEMM: 128x256 CTA tile, 512 thr, 1 CTA/SM -------
constexpr int TMW = 128;
constexpr int TNW = 256;
constexpr int KC  = 64;
constexpr int ATILE_W = 128 * 128;              // 16 KB
constexpr int BTILE_W = 256 * 128;              // 32 KB
constexpr int STAGE_W = ATILE_W + BTILE_W;      // 48 KB
constexpr int NSTW   = 3;
constexpr int SMEM_W = NSTW * STAGE_W;          // 147456 B

// ---------------- fused attention config (R14 proven) ----------------
constexpr int QT = 128;
constexpr int KT = 128;
constexpr int AOFF_ST = 32768;            // after Q (32 KB)
constexpr int ASTAGE_B = 65536;           // K (32K) + V (32K)
constexpr int ATT_SMEM = AOFF_ST + 2 * ASTAGE_B;  // 163840 B

// ---- scratch ----
__device__ f16  g_hh [(size_t)kM * kH];
__device__ f16  g_wh [4][(size_t)kH * kH];            // q,k,v,o
__device__ f16  g_qh [(size_t)kB * kNH * kS * kHD];   // [b,h,s,d]
__device__ f16  g_kh [(size_t)kB * kNH * kS * kHD];   // [b,h,s,d]
__device__ f16  g_vth[(size_t)kB * kNH * kHD * kS];   // [b,h,d,s]
__device__ f16  g_aoh[(size_t)kM * kH];               // attn out [b*s, h*HD+d]

// ---------------------------------------------------------------------------
__device__ __forceinline__ uint32_t smem_u32(const void* p) {
    uint32_t a;
    asm("{ .reg .u64 t; cvta.to.shared.u64 t, %1; cvt.u32.u64 %0, t; }"
        : "=r"(a) : "l"(p));
    return a;
}
__device__ __forceinline__ void ldsm4(uint32_t* d, uint32_t addr) {
    asm volatile("ldmatrix.sync.aligned.m8n8.x4.shared.b16 {%0,%1,%2,%3}, [%4];"
                 : "=r"(d[0]), "=r"(d[1]), "=r"(d[2]), "=r"(d[3]) : "r"(addr));
}
__device__ __forceinline__ void mma_f16(float* c, const uint32_t* a,
                                        const uint32_t* b) {
    asm volatile(
        "mma.sync.aligned.m16n8k16.row.col.f32.f16.f16.f32 "
        "{%0,%1,%2,%3}, {%4,%5,%6,%7}, {%8,%9}, {%0,%1,%2,%3};"
        : "+f"(c[0]), "+f"(c[1]), "+f"(c[2]), "+f"(c[3])
        : "r"(a[0]), "r"(a[1]), "r"(a[2]), "r"(a[3]), "r"(b[0]), "r"(b[1]));
}
__device__ __forceinline__ void cpa16(uint32_t dst, const void* src) {
    asm volatile("cp.async.cg.shared.global [%0], [%1], 16;"
                 :: "r"(dst), "l"(__cvta_generic_to_global(src)));
}
#define CP_COMMIT() asm volatile("cp.async.commit_group;" ::: "memory")

__device__ __forceinline__ uint32_t pkh(f16 a, f16 b) {
    __half2 t(a, b);
    return *reinterpret_cast<uint32_t*>(&t);
}
__device__ __forceinline__ void store4h(f16* dst, float x, float y, float z, float w) {
    uint2 v = {pkh(__float2half_rn(x), __float2half_rn(y)),
               pkh(__float2half_rn(z), __float2half_rn(w))};
    *reinterpret_cast<uint2*>(dst) = v;
}
__device__ __forceinline__ float ex2f(float x) {
    float y;
    asm("ex2.approx.ftz.f32 %0, %1;" : "=f"(y) : "f"(x));
    return y;
}
__device__ __forceinline__ uint32_t swz(int row, int ch) {
    return (uint32_t)(row * 128 + ((ch ^ (row & 7)) << 4));
}

// ---------------------------------------------------------------------------
// All fp32 -> fp16 conversions in ONE launch, MLP=4 per thread.
__global__ void __launch_bounds__(256)
split_all(const float4* __restrict__ hs,
          const float4* __restrict__ w0, const float4* __restrict__ w1,
          const float4* __restrict__ w2, const float4* __restrict__ w3,
          uint2* __restrict__ hh, uint2* __restrict__ wh)
{
    const int b = blockIdx.x;
    const float4* src;
    uint2* dst;
    int lb;
    if (b < 2048) { src = hs; dst = hh; lb = b; }
    else {
        const int w = (b - 2048) >> 10;
        lb = (b - 2048) & 1023;
        src = (w == 0) ? w0 : (w == 1) ? w1 : (w == 2) ? w2 : w3;
        dst = wh + (size_t)w * (kH * kH / 4);
    }
    const int base = lb * 1024 + threadIdx.x;
    float4 v[4];
    #pragma unroll
    for (int j = 0; j < 4; ++j) v[j] = src[base + j * 256];
    #pragma unroll
    for (int j = 0; j < 4; ++j)
        dst[base + j * 256] = {pkh(__float2half_rn(v[j].x), __float2half_rn(v[j].y)),
                               pkh(__float2half_rn(v[j].z), __float2half_rn(v[j].w))};
}

// ---------------------------------------------------------------------------
// Wide GEMM mainloop: 128x256 CTA tile, 512 threads (4x4 warps of 32x64),
// 3-stage cp.async (prefetch distance 2) + 1-ahead fragment double-buffering.
// Bytes/MAC = 0.114 vs 0.137 for the 64x128 config.
// ---------------------------------------------------------------------------
__device__ __forceinline__ void gemm_wide(const f16* __restrict__ Ah,
                                          const f16* __restrict__ Bh,
                                          int lda, int ldb, int m0, int n0,
                                          int NC, uint32_t sb,
                                          int tid, int lane, int wm, int wn,
                                          float acc[2][8][4])
{
    auto load_stage = [&](int c) {
        const uint32_t base = sb + (c % NSTW) * STAGE_W;
        const int k0 = c * KC;
        #pragma unroll
        for (int it = 0; it < 2; ++it) {          // A: 128 rows x 8 chunks
            const int idx = tid + it * 512;
            const int r = idx >> 3, ch = idx & 7;
            cpa16(base + swz(r, ch), Ah + (size_t)(m0 + r) * lda + k0 + ch * 8);
        }
        #pragma unroll
        for (int it = 0; it < 4; ++it) {          // B: 256 rows x 8 chunks
            const int idx = tid + it * 512;
            const int r = idx >> 3, ch = idx & 7;
            cpa16(base + ATILE_W + swz(r, ch),
                  Bh + (size_t)(n0 + r) * ldb + k0 + ch * 8);
        }
    };

    const int arow0 = wm + (lane & 15);
    const int arow1 = arow0 + 16;
    const int acsel = lane >> 4;
    const int brow_base = wn + (lane & 7) + ((lane >> 4) << 3);
    const int bcsel = (lane >> 3) & 1;

    load_stage(0); CP_COMMIT();
    if (NC > 1) load_stage(1);
    CP_COMMIT();

    for (int c = 0; c < NC; ++c) {
        if (c + 2 <= NC) asm volatile("cp.async.wait_group 1;" ::: "memory");
        else             asm volatile("cp.async.wait_group 0;" ::: "memory");
        __syncthreads();
        if (c + 2 < NC) { load_stage(c + 2); CP_COMMIT(); }

        const uint32_t ab = sb + (c % NSTW) * STAGE_W;
        const uint32_t bb = ab + ATILE_W;

        uint32_t af[2][2][4], bf[2][4][4];
        ldsm4(af[0][0], ab + swz(arow0, acsel));
        ldsm4(af[0][1], ab + swz(arow1, acsel));
        #pragma unroll
        for (int jj = 0; jj < 4; ++jj)
            ldsm4(bf[0][jj], bb + swz(brow_base + 16 * jj, bcsel));

        #pragma unroll
        for (int ks = 0; ks < KC / 16; ++ks) {
            const int cur = ks & 1, nxt = cur ^ 1;
            if (ks + 1 < KC / 16) {
                const int ch = 2 * (ks + 1);
                ldsm4(af[nxt][0], ab + swz(arow0, ch + acsel));
                ldsm4(af[nxt][1], ab + swz(arow1, ch + acsel));
                #pragma unroll
                for (int jj = 0; jj < 4; ++jj)
                    ldsm4(bf[nxt][jj], bb + swz(brow_base + 16 * jj, ch + bcsel));
            }
            #pragma unroll
            for (int jj = 0; jj < 4; ++jj)
                #pragma unroll
                for (int i = 0; i < 2; ++i)
                    #pragma unroll
                    for (int j2 = 0; j2 < 2; ++j2)
                        mma_f16(acc[i][2 * jj + j2], af[cur][i],
                                bf[cur][jj] + 2 * j2);
        }
    }
    __syncthreads();   // protect buffers before epilogue reuses smem
}

// Stage one 128-col half of the 128x256 tile into smem (fp32, stride 132).
__device__ __forceinline__ void stage_half(char* dsm, int lane, int wm, int wn,
                                           int half, float acc[2][8][4])
{
    float* ep = reinterpret_cast<float*>(dsm);
    if ((wn >> 7) == half) {
        const int wnl = wn & 127;
        #pragma unroll
        for (int i = 0; i < 2; ++i)
            #pragma unroll
            for (int j = 0; j < 8; ++j) {
                const int r0 = wm + 16 * i + (lane >> 2);
                const int c0 = wnl + 8 * j + 2 * (lane & 3);
                ep[r0 * 132 + c0]           = acc[i][j][0];
                ep[r0 * 132 + c0 + 1]       = acc[i][j][1];
                ep[(r0 + 8) * 132 + c0]     = acc[i][j][2];
                ep[(r0 + 8) * 132 + c0 + 1] = acc[i][j][3];
            }
    }
}

// ---------------------------------------------------------------------------
// Fused QKV projection: grid (24, 32); w = bx>>3, nb = bx&7, n0 = nb*256.
// ---------------------------------------------------------------------------
__global__ void __launch_bounds__(512, 1)
mm_qkv(const f16* __restrict__ hh, const f16* __restrict__ wh,
       f16* __restrict__ qh, f16* __restrict__ kh, f16* __restrict__ vth)
{
    extern __shared__ char dsm[];
    const int w  = blockIdx.x >> 3;
    const int nb = blockIdx.x & 7;
    const int m0 = blockIdx.y * TMW;
    const int n0 = nb * TNW;

    const int tid  = threadIdx.x;
    const int lane = tid & 31;
    const int wid  = tid >> 5;
    const int wm   = (wid & 3) * 32;
    const int wn   = (wid >> 2) * 64;
    const uint32_t sb = smem_u32(dsm);

    float acc[2][8][4];
    #pragma unroll
    for (int i = 0; i < 2; ++i)
        #pragma unroll
        for (int j = 0; j < 8; ++j)
            #pragma unroll
            for (int t = 0; t < 4; ++t) acc[i][j][t] = 0.f;

    const f16* Bh = wh + (size_t)w * kH * kH;
    gemm_wide(hh, Bh, kH, kH, m0, n0, kH / KC, sb, tid, lane, wm, wn, acc);

    float* ep = reinterpret_cast<float*>(dsm);
    #pragma unroll
    for (int half = 0; half < 2; ++half) {
        stage_half(dsm, lane, wm, wn, half, acc);
        __syncthreads();

        const int head = nb * 2 + half;
        if (w == 2) {
            // V transposed: [b,h,d,s]; thread = (d, 32-s segment)
            const int d    = tid >> 2;         // 0..127
            const int mseg = (tid & 3) * 32;
            const int b = m0 >> 11;
            const size_t base = ((size_t)((b * kNH + head) * kHD + d)) * kS +
                                (m0 & (kS - 1)) + mseg;
            #pragma unroll
            for (int j = 0; j < 8; ++j) {
                store4h(vth + base + 4 * j,
                        ep[(mseg + 4 * j + 0) * 132 + d],
                        ep[(mseg + 4 * j + 1) * 132 + d],
                        ep[(mseg + 4 * j + 2) * 132 + d],
                        ep[(mseg + 4 * j + 3) * 132 + d]);
            }
        } else {
            f16* Ch = (w == 0) ? qh : kh;
            const int r   = tid >> 2;          // 0..127
            const int c0  = (tid & 3) * 32;
            const int row = m0 + r;
            const int b = row >> 11, s = row & (kS - 1);
            const size_t base = ((size_t)((b * kNH + head) * kS + s)) * kHD + c0;
            #pragma unroll
            for (int j = 0; j < 8; ++j) {
                const int cc = 4 * j;
                store4h(Ch + base + cc,
                        ep[r * 132 + c0 + cc + 0], ep[r * 132 + c0 + cc + 1],
                        ep[r * 132 + c0 + cc + 2], ep[r * 132 + c0 + cc + 3]);
            }
        }
        __syncthreads();
    }
}

// ---------------------------------------------------------------------------
// Output projection: fp16 in -> fp32 out, row-major. grid (8, 32).
// ---------------------------------------------------------------------------
__global__ void __launch_bounds__(512, 1)
mm_o(const f16* __restrict__ Ah, const f16* __restrict__ Bh,
     float* __restrict__ Cf)
{
    extern __shared__ char dsm[];
    const int m0 = blockIdx.y * TMW;
    const int n0 = blockIdx.x * TNW;

    const int tid  = threadIdx.x;
    const int lane = tid & 31;
    const int wid  = tid >> 5;
    const int wm   = (wid & 3) * 32;
    const int wn   = (wid >> 2) * 64;
    const uint32_t sb = smem_u32(dsm);

    float acc[2][8][4];
    #pragma unroll
    for (int i = 0; i < 2; ++i)
        #pragma unroll
        for (int j = 0; j < 8; ++j)
            #pragma unroll
            for (int t = 0; t < 4; ++t) acc[i][j][t] = 0.f;

    gemm_wide(Ah, Bh, kH, kH, m0, n0, kH / KC, sb, tid, lane, wm, wn, acc);

    float* ep = reinterpret_cast<float*>(dsm);
    #pragma unroll
    for (int half = 0; half < 2; ++half) {
        stage_half(dsm, lane, wm, wn, half, acc);
        __syncthreads();

        const int r  = tid >> 2;               // 0..127
        const int c0 = (tid & 3) * 32;
        const size_t base = (size_t)(m0 + r) * kH + n0 + 128 * half + c0;
        #pragma unroll
        for (int j = 0; j < 8; ++j) {
            const int cc = 4 * j;
            float4 v = {ep[r * 132 + c0 + cc + 0], ep[r * 132 + c0 + cc + 1],
                        ep[r * 132 + c0 + cc + 2], ep[r * 132 + c0 + cc + 3]};
            *reinterpret_cast<float4*>(Cf + base + cc) = v;
        }
        __syncthreads();
    }
}

// ---------------------------------------------------------------------------
// Fused flash attention (R14 proven): q-tile 128, kv-step 128, double-buffered
// cp.async, persistent Q fragments, 1-ahead ldsm pipelining, tensor-core sums.
// ---------------------------------------------------------------------------
__global__ void __launch_bounds__(256, 1)
fattn_k(const f16* __restrict__ Qg, const f16* __restrict__ Kg,
        const f16* __restrict__ Vtg, f16* __restrict__ Og)
{
    extern __shared__ char dsm[];
    const int bh = blockIdx.y;
    const int qt = gridDim.x - 1 - blockIdx.x;   // longest CTAs first
    const int q0 = qt * QT;
    const int nsteps = qt + 1;
    const int b = bh >> 4, h = bh & 15;

    const f16* Qp = Qg  + (size_t)bh * kS * kHD;
    const f16* Kp = Kg  + (size_t)bh * kS * kHD;
    const f16* Vp = Vtg + (size_t)bh * kHD * kS;

    const int tid = threadIdx.x, lane = tid & 31, wid = tid >> 5;
    const int wr = wid * 16;
    const uint32_t sb = smem_u32(dsm);

    #pragma unroll
    for (int it = 0; it < 8; ++it) {
        const int idx = tid + it * 256;
        const int r = idx >> 4, ch = idx & 15;
        cpa16(sb + (ch >> 3) * 16384 + swz(r, ch & 7),
              Qp + (size_t)(q0 + r) * kHD + ch * 8);
    }
    auto load_stage = [&](int c) {
        const uint32_t base = sb + AOFF_ST + (c & 1) * ASTAGE_B;
        const int kv0 = c * KT;
        #pragma unroll
        for (int it = 0; it < 8; ++it) {
            const int idx = tid + it * 256;
            const int r = idx >> 4, ch = idx & 15;
            cpa16(base + (ch >> 3) * 16384 + swz(r, ch & 7),
                  Kp + (size_t)(kv0 + r) * kHD + ch * 8);
        }
        #pragma unroll
        for (int it = 0; it < 8; ++it) {
            const int idx = tid + it * 256;
            const int r = idx >> 4, ch = idx & 15;
            cpa16(base + 32768 + (ch >> 3) * 16384 + swz(r, ch & 7),
                  Vp + (size_t)r * kS + kv0 + ch * 8);
        }
    };
    load_stage(0); CP_COMMIT();

    float oacc[16][4];
    #pragma unroll
    for (int n = 0; n < 16; ++n)
        #pragma unroll
        for (int t = 0; t < 4; ++t) oacc[n][t] = 0.f;
    float lacc[4] = {0.f, 0.f, 0.f, 0.f};       // tensor-core row sums
    float m0 = -1e30f, m1 = -1e30f;

    uint32_t qf[8][4];                          // persistent Q fragments
    const uint32_t bones[2] = {0x3C003C00u, 0x3C003C00u};  // 1.0h x4

    constexpr float CEXP = 0.12751791441801597f;  // 128^-0.5 * log2(e)

    const int brow_base = (lane & 7) + ((lane >> 4) << 3);
    const int bcsel = (lane >> 3) & 1;

    for (int c = 0; c < nsteps; ++c) {
        if (c + 1 < nsteps) {
            load_stage(c + 1); CP_COMMIT();
            asm volatile("cp.async.wait_group 1;" ::: "memory");
        } else {
            asm volatile("cp.async.wait_group 0;" ::: "memory");
        }
        __syncthreads();

        if (c == 0) {
            #pragma unroll
            for (int kc = 0; kc < 8; ++kc) {
                const int row = wr + (lane & 15);
                const int c16 = 2 * kc + (lane >> 4);
                ldsm4(qf[kc], sb + (c16 >> 3) * 16384 + swz(row, c16 & 7));
            }
        }

        const uint32_t kb = sb + AOFF_ST + (c & 1) * ASTAGE_B;
        const uint32_t vb = kb + 32768;

        float sacc[16][4];
        #pragma unroll
        for (int j = 0; j < 16; ++j)
            #pragma unroll
            for (int t = 0; t < 4; ++t) sacc[j][t] = 0.f;

        #pragma unroll
        for (int kc = 0; kc < 8; ++kc) {
            const int c16 = 2 * kc + bcsel;
            uint32_t bf[2][4];
            ldsm4(bf[0], kb + (c16 >> 3) * 16384 + swz(brow_base, c16 & 7));
            #pragma unroll
            for (int jj2 = 0; jj2 < 8; ++jj2) {
                const int cur = jj2 & 1, nxt = cur ^ 1;
                if (jj2 + 1 < 8) {
                    const int row = 16 * (jj2 + 1) + brow_base;
                    ldsm4(bf[nxt], kb + (c16 >> 3) * 16384 + swz(row, c16 & 7));
                }
                mma_f16(sacc[2 * jj2],     qf[kc], bf[cur]);
                mma_f16(sacc[2 * jj2 + 1], qf[kc], bf[cur] + 2);
            }
        }

        if (c == nsteps - 1) {
            const int r0l = wr + (lane >> 2);
            const int r1l = r0l + 8;
            #pragma unroll
            for (int jj = 0; jj < 16; ++jj) {
                const int cb = 8 * jj + 2 * (lane & 3);
                if (cb     > r0l) sacc[jj][0] = -1e30f;
                if (cb + 1 > r0l) sacc[jj][1] = -1e30f;
                if (cb     > r1l) sacc[jj][2] = -1e30f;
                if (cb + 1 > r1l) sacc[jj][3] = -1e30f;
            }
        }

        float mx0 = -1e30f, mx1 = -1e30f;
        #pragma unroll
        for (int jj = 0; jj < 16; ++jj) {
            mx0 = fmaxf(mx0, fmaxf(sacc[jj][0], sacc[jj][1]));
            mx1 = fmaxf(mx1, fmaxf(sacc[jj][2], sacc[jj][3]));
        }
        mx0 = fmaxf(mx0, __shfl_xor_sync(0xFFFFFFFFu, mx0, 1));
        mx0 = fmaxf(mx0, __shfl_xor_sync(0xFFFFFFFFu, mx0, 2));
        mx1 = fmaxf(mx1, __shfl_xor_sync(0xFFFFFFFFu, mx1, 1));
        mx1 = fmaxf(mx1, __shfl_xor_sync(0xFFFFFFFFu, mx1, 2));

        const float mn0 = fmaxf(m0, mx0);
        const float mn1 = fmaxf(m1, mx1);
        const float a0 = ex2f((m0 - mn0) * CEXP);
        const float a1 = ex2f((m1 - mn1) * CEXP);
        m0 = mn0; m1 = mn1;

        #pragma unroll
        for (int jj = 0; jj < 16; ++jj) {
            sacc[jj][0] = ex2f((sacc[jj][0] - m0) * CEXP);
            sacc[jj][1] = ex2f((sacc[jj][1] - m0) * CEXP);
            sacc[jj][2] = ex2f((sacc[jj][2] - m1) * CEXP);
            sacc[jj][3] = ex2f((sacc[jj][3] - m1) * CEXP);
        }

        #pragma unroll
        for (int n = 0; n < 16; ++n) {
            oacc[n][0] *= a0; oacc[n][1] *= a0;
            oacc[n][2] *= a1; oacc[n][3] *= a1;
        }
        lacc[0] *= a0; lacc[1] *= a0;
        lacc[2] *= a1; lacc[3] *= a1;

        #pragma unroll
        for (int kc2 = 0; kc2 < 8; ++kc2) {
            uint32_t ap[4];
            ap[0] = pkh(__float2half_rn(sacc[2 * kc2][0]),
                        __float2half_rn(sacc[2 * kc2][1]));
            ap[1] = pkh(__float2half_rn(sacc[2 * kc2][2]),
                        __float2half_rn(sacc[2 * kc2][3]));
            ap[2] = pkh(__float2half_rn(sacc[2 * kc2 + 1][0]),
                        __float2half_rn(sacc[2 * kc2 + 1][1]));
            ap[3] = pkh(__float2half_rn(sacc[2 * kc2 + 1][2]),
                        __float2half_rn(sacc[2 * kc2 + 1][3]));
            const int c16 = 2 * kc2 + bcsel;
            uint32_t bf[2][4];
            ldsm4(bf[0], vb + (c16 >> 3) * 16384 + swz(brow_base, c16 & 7));
            #pragma unroll
            for (int nn2 = 0; nn2 < 8; ++nn2) {
                const int cur = nn2 & 1, nxt = cur ^ 1;
                if (nn2 + 1 < 8) {
                    const int row = 16 * (nn2 + 1) + brow_base;
                    ldsm4(bf[nxt], vb + (c16 >> 3) * 16384 + swz(row, c16 & 7));
                }
                mma_f16(oacc[2 * nn2],     ap, bf[cur]);
                mma_f16(oacc[2 * nn2 + 1], ap, bf[cur] + 2);
            }
            mma_f16(lacc, ap, bones);         // row sums via tensor core
        }
        __syncthreads();
    }

    const float i0 = 1.f / lacc[0];
    const float i1 = 1.f / lacc[2];
    const int r0g = q0 + wr + (lane >> 2);
    f16* o0 = Og + (size_t)(b * kS + r0g) * kH + h * kHD;
    f16* o1 = Og + (size_t)(b * kS + r0g + 8) * kH + h * kHD;
    #pragma unroll
    for (int nb = 0; nb < 16; ++nb) {
        const int col = 8 * nb + 2 * (lane & 3);
        *reinterpret_cast<uint32_t*>(o0 + col) =
            pkh(__float2half_rn(oacc[nb][0] * i0),
                __float2half_rn(oacc[nb][1] * i0));
        *reinterpret_cast<uint32_t*>(o1 + col) =
            pkh(__float2half_rn(oacc[nb][2] * i1),
                __float2half_rn(oacc[nb][3] * i1));
    }
}

// ---------------------------------------------------------------------------
extern "C" void kernel_launch(void* const* d_in, const int* in_sizes, int n_in,
                              void* d_out, int out_size)
{
    const float* hs = (const float*)d_in[0];
    // d_in[1] = attention_mask (causal; applied analytically)
    const float* W[4] = {(const float*)d_in[2], (const float*)d_in[3],
                         (const float*)d_in[4], (const float*)d_in[5]};
    float* out = (float*)d_out;

    f16 *hh, *wh, *qh, *kh, *vth, *aoh;
    cudaGetSymbolAddress((void**)&hh,  g_hh);
    cudaGetSymbolAddress((void**)&wh,  g_wh);
    cudaGetSymbolAddress((void**)&qh,  g_qh);
    cudaGetSymbolAddress((void**)&kh,  g_kh);
    cudaGetSymbolAddress((void**)&vth, g_vth);
    cudaGetSymbolAddress((void**)&aoh, g_aoh);

    cudaFuncSetAttribute(mm_qkv, cudaFuncAttributeMaxDynamicSharedMemorySize, SMEM_W);
    cudaFuncSetAttribute(mm_o,   cudaFuncAttributeMaxDynamicSharedMemorySize, SMEM_W);
    cudaFuncSetAttribute(fattn_k, cudaFuncAttributeMaxDynamicSharedMemorySize, ATT_SMEM);

    const size_t WN = (size_t)kH * kH;

    split_all<<<2048 + 4 * 1024, 256>>>((const float4*)hs,
                                        (const float4*)W[0], (const float4*)W[1],
                                        (const float4*)W[2], (const float4*)W[3],
                                        (uint2*)hh, (uint2*)wh);

    // Fused Q,K,V projections: 24 x 32 CTAs of 512 threads
    mm_qkv<<<dim3(24, kM / TMW), 512, SMEM_W>>>(hh, wh, qh, kh, vth);

    // Fused scores + softmax + PV
    fattn_k<<<dim3(kS / QT, kB * kNH), 256, ATT_SMEM>>>(qh, kh, vth, aoh);

    // Output projection: 8 x 32 CTAs
    mm_o<<<dim3(kH / TNW, kM / TMW), 512, SMEM_W>>>(aoh, wh + 3 * WN, out);
}

// round 17
// speedup vs baseline: 1.1512x; 1.1512x over previous
#include <cuda_runtime.h>
#include <cuda_fp16.h>
#include <cstdint>
#include <cstddef>

using f16 = __half;

constexpr int kB  = 2;
constexpr int kS  = 2048;
constexpr int kH  = 2048;
constexpr int kNH = 16;
constexpr int kHD = 128;
constexpr int kM  = kB * kS;   // 4096

// ---------------- projection GEMM config: 64x128 CTA tile, 4 CTAs/SM -------
constexpr int TMG = 64;
constexpr int TNG = 128;
constexpr int KC  = 64;
constexpr int ATILE_G = 64 * 128;               // 8 KB
constexpr int BTILE_G = 128 * 128;              // 16 KB
constexpr int STAGE_G = ATILE_G + BTILE_G;      // 24 KB
constexpr int SMEM_G  = 2 * STAGE_G;            // 49152 B

// ---------------- fused attention config ----------------
constexpr int QT = 128;
constexpr int KT = 128;
constexpr int AOFF_ST = 32768;            // after Q (32 KB)
constexpr int ASTAGE_B = 65536;           // K (32K) + V (32K)
constexpr int ATT_SMEM = AOFF_ST + 2 * ASTAGE_B;  // 163840 B

// ---- scratch ----
__device__ f16  g_hh [(size_t)kM * kH];
__device__ f16  g_wh [4][(size_t)kH * kH];            // q,k,v,o
__device__ f16  g_qh [(size_t)kB * kNH * kS * kHD];   // [b,h,s,d]
__device__ f16  g_kh [(size_t)kB * kNH * kS * kHD];   // [b,h,s,d]
__device__ f16  g_vth[(size_t)kB * kNH * kHD * kS];   // [b,h,d,s]
__device__ f16  g_aoh[(size_t)kM * kH];               // attn out [b*s, h*HD+d]

// ---------------------------------------------------------------------------
__device__ __forceinline__ uint32_t smem_u32(const void* p) {
    uint32_t a;
    asm("{ .reg .u64 t; cvta.to.shared.u64 t, %1; cvt.u32.u64 %0, t; }"
        : "=r"(a) : "l"(p));
    return a;
}
__device__ __forceinline__ void ldsm4(uint32_t* d, uint32_t addr) {
    asm volatile("ldmatrix.sync.aligned.m8n8.x4.shared.b16 {%0,%1,%2,%3}, [%4];"
                 : "=r"(d[0]), "=r"(d[1]), "=r"(d[2]), "=r"(d[3]) : "r"(addr));
}
__device__ __forceinline__ void mma_f16(float* c, const uint32_t* a,
                                        const uint32_t* b) {
    asm volatile(
        "mma.sync.aligned.m16n8k16.row.col.f32.f16.f16.f32 "
        "{%0,%1,%2,%3}, {%4,%5,%6,%7}, {%8,%9}, {%0,%1,%2,%3};"
        : "+f"(c[0]), "+f"(c[1]), "+f"(c[2]), "+f"(c[3])
        : "r"(a[0]), "r"(a[1]), "r"(a[2]), "r"(a[3]), "r"(b[0]), "r"(b[1]));
}
__device__ __forceinline__ void cpa16(uint32_t dst, const void* src) {
    asm volatile("cp.async.cg.shared.global [%0], [%1], 16;"
                 :: "r"(dst), "l"(__cvta_generic_to_global(src)));
}
#define CP_COMMIT() asm volatile("cp.async.commit_group;" ::: "memory")

__device__ __forceinline__ uint32_t pkh(f16 a, f16 b) {
    __half2 t(a, b);
    return *reinterpret_cast<uint32_t*>(&t);
}
__device__ __forceinline__ void store4h(f16* dst, float x, float y, float z, float w) {
    uint2 v = {pkh(__float2half_rn(x), __float2half_rn(y)),
               pkh(__float2half_rn(z), __float2half_rn(w))};
    *reinterpret_cast<uint2*>(dst) = v;
}
__device__ __forceinline__ float ex2f(float x) {
    float y;
    asm("ex2.approx.ftz.f32 %0, %1;" : "=f"(y) : "f"(x));
    return y;
}
__device__ __forceinline__ uint32_t swz(int row, int ch) {
    return (uint32_t)(row * 128 + ((ch ^ (row & 7)) << 4));
}

// ---------------------------------------------------------------------------
// All fp32 -> fp16 conversions in ONE launch, MLP=4 per thread.
//   blocks [0, 2048)        : hidden (4096x2048), 1024 float4 per block
//   blocks [2048 + w*1024..): weight w (2048x2048)
__global__ void __launch_bounds__(256)
split_all(const float4* __restrict__ hs,
          const float4* __restrict__ w0, const float4* __restrict__ w1,
          const float4* __restrict__ w2, const float4* __restrict__ w3,
          uint2* __restrict__ hh, uint2* __restrict__ wh)
{
    const int b = blockIdx.x;
    const float4* src;
    uint2* dst;
    int lb;
    if (b < 2048) { src = hs; dst = hh; lb = b; }
    else {
        const int w = (b - 2048) >> 10;
        lb = (b - 2048) & 1023;
        src = (w == 0) ? w0 : (w == 1) ? w1 : (w == 2) ? w2 : w3;
        dst = wh + (size_t)w * (kH * kH / 4);
    }
    const int base = lb * 1024 + threadIdx.x;
    float4 v[4];
    #pragma unroll
    for (int j = 0; j < 4; ++j) v[j] = src[base + j * 256];
    #pragma unroll
    for (int j = 0; j < 4; ++j)
        dst[base + j * 256] = {pkh(__float2half_rn(v[j].x), __float2half_rn(v[j].y)),
                               pkh(__float2half_rn(v[j].z), __float2half_rn(v[j].w))};
}

// ---------------------------------------------------------------------------
// GEMM mainloop (R14 proven): 64x128 CTA tile, 128 threads (2x2 warps of
// 32x64), double-buffered cp.async + 1-ahead fragment double-buffering.
// ---------------------------------------------------------------------------
__device__ __forceinline__ void gemm_core(const f16* __restrict__ Ah,
                                          const f16* __restrict__ Bh,
                                          int lda, int ldb, int m0, int n0,
                                          int NC, uint32_t sb,
                                          int tid, int lane, int wm, int wn,
                                          float acc[2][8][4])
{
    auto load_stage = [&](int c) {
        const uint32_t base = sb + (c & 1) * STAGE_G;
        const int k0 = c * KC;
        #pragma unroll
        for (int it = 0; it < 4; ++it) {
            const int idx = tid + it * 128;
            const int r = idx >> 3, ch = idx & 7;
            cpa16(base + swz(r, ch), Ah + (size_t)(m0 + r) * lda + k0 + ch * 8);
        }
        #pragma unroll
        for (int it = 0; it < 8; ++it) {
            const int idx = tid + it * 128;
            const int r = idx >> 3, ch = idx & 7;
            cpa16(base + ATILE_G + swz(r, ch),
                  Bh + (size_t)(n0 + r) * ldb + k0 + ch * 8);
        }
    };

    const int arow0 = wm + (lane & 15);
    const int arow1 = arow0 + 16;
    const int acsel = lane >> 4;
    const int brow_base = wn + (lane & 7) + ((lane >> 4) << 3);
    const int bcsel = (lane >> 3) & 1;

    load_stage(0); CP_COMMIT();

    for (int c = 0; c < NC; ++c) {
        asm volatile("cp.async.wait_group 0;" ::: "memory");
        __syncthreads();
        if (c + 1 < NC) { load_stage(c + 1); CP_COMMIT(); }

        const uint32_t ab = sb + (c & 1) * STAGE_G;
        const uint32_t bb = ab + ATILE_G;

        uint32_t af[2][2][4], bf[2][4][4];
        ldsm4(af[0][0], ab + swz(arow0, acsel));
        ldsm4(af[0][1], ab + swz(arow1, acsel));
        #pragma unroll
        for (int jj = 0; jj < 4; ++jj)
            ldsm4(bf[0][jj], bb + swz(brow_base + 16 * jj, bcsel));

        #pragma unroll
        for (int ks = 0; ks < KC / 16; ++ks) {
            const int cur = ks & 1, nxt = cur ^ 1;
            if (ks + 1 < KC / 16) {
                const int ch = 2 * (ks + 1);
                ldsm4(af[nxt][0], ab + swz(arow0, ch + acsel));
                ldsm4(af[nxt][1], ab + swz(arow1, ch + acsel));
                #pragma unroll
                for (int jj = 0; jj < 4; ++jj)
                    ldsm4(bf[nxt][jj], bb + swz(brow_base + 16 * jj, ch + bcsel));
            }
            #pragma unroll
            for (int jj = 0; jj < 4; ++jj)
                #pragma unroll
                for (int i = 0; i < 2; ++i)
                    #pragma unroll
                    for (int j2 = 0; j2 < 2; ++j2)
                        mma_f16(acc[i][2 * jj + j2], af[cur][i],
                                bf[cur][jj] + 2 * j2);
        }
    }
    __syncthreads();   // protect buffers before epilogue reuses smem
}

// Stage 64x128 accumulators into smem (fp32, stride 132).
__device__ __forceinline__ void stage_acc(char* dsm, int lane, int wm, int wn,
                                          float acc[2][8][4])
{
    float* ep = reinterpret_cast<float*>(dsm);
    #pragma unroll
    for (int i = 0; i < 2; ++i)
        #pragma unroll
        for (int j = 0; j < 8; ++j) {
            const int r0 = wm + 16 * i + (lane >> 2);
            const int c0 = wn + 8 * j + 2 * (lane & 3);
            ep[r0 * 132 + c0]           = acc[i][j][0];
            ep[r0 * 132 + c0 + 1]       = acc[i][j][1];
            ep[(r0 + 8) * 132 + c0]     = acc[i][j][2];
            ep[(r0 + 8) * 132 + c0 + 1] = acc[i][j][3];
        }
}

// ---------------------------------------------------------------------------
// Fused QKV projection: grid (48, 64); w = bx>>4, nb = bx&15, m0 = by*64.
// ---------------------------------------------------------------------------
__global__ void __launch_bounds__(128, 4)
mm_qkv(const f16* __restrict__ hh, const f16* __restrict__ wh,
       f16* __restrict__ qh, f16* __restrict__ kh, f16* __restrict__ vth)
{
    extern __shared__ char dsm[];
    const int w  = blockIdx.x >> 4;
    const int nb = blockIdx.x & 15;
    const int m0 = blockIdx.y * TMG;
    const int n0 = nb * TNG;

    const int tid  = threadIdx.x;
    const int lane = tid & 31;
    const int wid  = tid >> 5;
    const int wm   = (wid & 1) * 32;
    const int wn   = (wid >> 1) * 64;
    const uint32_t sb = smem_u32(dsm);

    float acc[2][8][4];
    #pragma unroll
    for (int i = 0; i < 2; ++i)
        #pragma unroll
        for (int j = 0; j < 8; ++j)
            #pragma unroll
            for (int t = 0; t < 4; ++t) acc[i][j][t] = 0.f;

    const f16* Bh = wh + (size_t)w * kH * kH;
    gemm_core(hh, Bh, kH, kH, m0, n0, kH / KC, sb, tid, lane, wm, wn, acc);

    stage_acc(dsm, lane, wm, wn, acc);
    __syncthreads();

    float* ep = reinterpret_cast<float*>(dsm);
    if (w == 2) {
        const int d = tid;                     // 0..127
        const int h = nb, b = m0 >> 11;
        const size_t base = ((size_t)((b * kNH + h) * kHD + d)) * kS +
                            (m0 & (kS - 1));
        #pragma unroll
        for (int j = 0; j < 16; ++j) {
            store4h(vth + base + 4 * j,
                    ep[(4 * j + 0) * 132 + d],
                    ep[(4 * j + 1) * 132 + d],
                    ep[(4 * j + 2) * 132 + d],
                    ep[(4 * j + 3) * 132 + d]);
        }
    } else {
        f16* Ch = (w == 0) ? qh : kh;
        const int r   = tid >> 1;              // 0..63
        const int c0  = (tid & 1) * 64;
        const int row = m0 + r;
        const int b = row >> 11, s = row & (kS - 1), h = nb;
        const size_t base = ((size_t)((b * kNH + h) * kS + s)) * kHD + c0;
        #pragma unroll
        for (int j = 0; j < 16; ++j) {
            const int cc = 4 * j;
            store4h(Ch + base + cc,
                    ep[r * 132 + c0 + cc + 0], ep[r * 132 + c0 + cc + 1],
                    ep[r * 132 + c0 + cc + 2], ep[r * 132 + c0 + cc + 3]);
        }
    }
}

// ---------------------------------------------------------------------------
// Output projection: fp16 in -> fp32 out, row-major. grid (16, 64).
// ---------------------------------------------------------------------------
__global__ void __launch_bounds__(128, 4)
mm_o(const f16* __restrict__ Ah, const f16* __restrict__ Bh,
     float* __restrict__ Cf)
{
    extern __shared__ char dsm[];
    const int m0 = blockIdx.y * TMG;
    const int n0 = blockIdx.x * TNG;

    const int tid  = threadIdx.x;
    const int lane = tid & 31;
    const int wid  = tid >> 5;
    const int wm   = (wid & 1) * 32;
    const int wn   = (wid >> 1) * 64;
    const uint32_t sb = smem_u32(dsm);

    float acc[2][8][4];
    #pragma unroll
    for (int i = 0; i < 2; ++i)
        #pragma unroll
        for (int j = 0; j < 8; ++j)
            #pragma unroll
            for (int t = 0; t < 4; ++t) acc[i][j][t] = 0.f;

    gemm_core(Ah, Bh, kH, kH, m0, n0, kH / KC, sb, tid, lane, wm, wn, acc);

    stage_acc(dsm, lane, wm, wn, acc);
    __syncthreads();

    float* ep = reinterpret_cast<float*>(dsm);
    const int r  = tid >> 1;                   // 0..63
    const int c0 = (tid & 1) * 64;
    const size_t base = (size_t)(m0 + r) * kH + n0;
    #pragma unroll
    for (int j = 0; j < 16; ++j) {
        const int cc = c0 + 4 * j;
        float4 v = {ep[r * 132 + cc + 0], ep[r * 132 + cc + 1],
                    ep[r * 132 + cc + 2], ep[r * 132 + cc + 3]};
        *reinterpret_cast<float4*>(Cf + base + cc) = v;
    }
}

// ---------------------------------------------------------------------------
// Fused flash attention (R14 proven): q-tile 128, kv-step 128, double-buffered
// cp.async, persistent Q fragments, 1-ahead ldsm pipelining, tensor-core sums.
// ---------------------------------------------------------------------------
__global__ void __launch_bounds__(256, 1)
fattn_k(const f16* __restrict__ Qg, const f16* __restrict__ Kg,
        const f16* __restrict__ Vtg, f16* __restrict__ Og)
{
    extern __shared__ char dsm[];
    const int bh = blockIdx.y;
    const int qt = gridDim.x - 1 - blockIdx.x;   // longest CTAs first
    const int q0 = qt * QT;
    const int nsteps = qt + 1;
    const int b = bh >> 4, h = bh & 15;

    const f16* Qp = Qg  + (size_t)bh * kS * kHD;
    const f16* Kp = Kg  + (size_t)bh * kS * kHD;
    const f16* Vp = Vtg + (size_t)bh * kHD * kS;

    const int tid = threadIdx.x, lane = tid & 31, wid = tid >> 5;
    const int wr = wid * 16;
    const uint32_t sb = smem_u32(dsm);

    #pragma unroll
    for (int it = 0; it < 8; ++it) {
        const int idx = tid + it * 256;
        const int r = idx >> 4, ch = idx & 15;
        cpa16(sb + (ch >> 3) * 16384 + swz(r, ch & 7),
              Qp + (size_t)(q0 + r) * kHD + ch * 8);
    }
    auto load_stage = [&](int c) {
        const uint32_t base = sb + AOFF_ST + (c & 1) * ASTAGE_B;
        const int kv0 = c * KT;
        #pragma unroll
        for (int it = 0; it < 8; ++it) {
            const int idx = tid + it * 256;
            const int r = idx >> 4, ch = idx & 15;
            cpa16(base + (ch >> 3) * 16384 + swz(r, ch & 7),
                  Kp + (size_t)(kv0 + r) * kHD + ch * 8);
        }
        #pragma unroll
        for (int it = 0; it < 8; ++it) {
            const int idx = tid + it * 256;
            const int r = idx >> 4, ch = idx & 15;
            cpa16(base + 32768 + (ch >> 3) * 16384 + swz(r, ch & 7),
                  Vp + (size_t)r * kS + kv0 + ch * 8);
        }
    };
    load_stage(0); CP_COMMIT();

    float oacc[16][4];
    #pragma unroll
    for (int n = 0; n < 16; ++n)
        #pragma unroll
        for (int t = 0; t < 4; ++t) oacc[n][t] = 0.f;
    float lacc[4] = {0.f, 0.f, 0.f, 0.f};       // tensor-core row sums
    float m0 = -1e30f, m1 = -1e30f;

    uint32_t qf[8][4];                          // persistent Q fragments
    const uint32_t bones[2] = {0x3C003C00u, 0x3C003C00u};  // 1.0h x4

    constexpr float CEXP = 0.12751791441801597f;  // 128^-0.5 * log2(e)

    const int brow_base = (lane & 7) + ((lane >> 4) << 3);
    const int bcsel = (lane >> 3) & 1;

    for (int c = 0; c < nsteps; ++c) {
        if (c + 1 < nsteps) {
            load_stage(c + 1); CP_COMMIT();
            asm volatile("cp.async.wait_group 1;" ::: "memory");
        } else {
            asm volatile("cp.async.wait_group 0;" ::: "memory");
        }
        __syncthreads();

        if (c == 0) {
            #pragma unroll
            for (int kc = 0; kc < 8; ++kc) {
                const int row = wr + (lane & 15);
                const int c16 = 2 * kc + (lane >> 4);
                ldsm4(qf[kc], sb + (c16 >> 3) * 16384 + swz(row, c16 & 7));
            }
        }

        const uint32_t kb = sb + AOFF_ST + (c & 1) * ASTAGE_B;
        const uint32_t vb = kb + 32768;

        float sacc[16][4];
        #pragma unroll
        for (int j = 0; j < 16; ++j)
            #pragma unroll
            for (int t = 0; t < 4; ++t) sacc[j][t] = 0.f;

        #pragma unroll
        for (int kc = 0; kc < 8; ++kc) {
            const int c16 = 2 * kc + bcsel;
            uint32_t bf[2][4];
            ldsm4(bf[0], kb + (c16 >> 3) * 16384 + swz(brow_base, c16 & 7));
            #pragma unroll
            for (int jj2 = 0; jj2 < 8; ++jj2) {
                const int cur = jj2 & 1, nxt = cur ^ 1;
                if (jj2 + 1 < 8) {
                    const int row = 16 * (jj2 + 1) + brow_base;
                    ldsm4(bf[nxt], kb + (c16 >> 3) * 16384 + swz(row, c16 & 7));
                }
                mma_f16(sacc[2 * jj2],     qf[kc], bf[cur]);
                mma_f16(sacc[2 * jj2 + 1], qf[kc], bf[cur] + 2);
            }
        }

        if (c == nsteps - 1) {
            const int r0l = wr + (lane >> 2);
            const int r1l = r0l + 8;
            #pragma unroll
            for (int jj = 0; jj < 16; ++jj) {
                const int cb = 8 * jj + 2 * (lane & 3);
                if (cb     > r0l) sacc[jj][0] = -1e30f;
                if (cb + 1 > r0l) sacc[jj][1] = -1e30f;
                if (cb     > r1l) sacc[jj][2] = -1e30f;
                if (cb + 1 > r1l) sacc[jj][3] = -1e30f;
            }
        }

        float mx0 = -1e30f, mx1 = -1e30f;
        #pragma unroll
        for (int jj = 0; jj < 16; ++jj) {
            mx0 = fmaxf(mx0, fmaxf(sacc[jj][0], sacc[jj][1]));
            mx1 = fmaxf(mx1, fmaxf(sacc[jj][2], sacc[jj][3]));
        }
        mx0 = fmaxf(mx0, __shfl_xor_sync(0xFFFFFFFFu, mx0, 1));
        mx0 = fmaxf(mx0, __shfl_xor_sync(0xFFFFFFFFu, mx0, 2));
        mx1 = fmaxf(mx1, __shfl_xor_sync(0xFFFFFFFFu, mx1, 1));
        mx1 = fmaxf(mx1, __shfl_xor_sync(0xFFFFFFFFu, mx1, 2));

        const float mn0 = fmaxf(m0, mx0);
        const float mn1 = fmaxf(m1, mx1);
        const float a0 = ex2f((m0 - mn0) * CEXP);
        const float a1 = ex2f((m1 - mn1) * CEXP);
        m0 = mn0; m1 = mn1;

        #pragma unroll
        for (int jj = 0; jj < 16; ++jj) {
            sacc[jj][0] = ex2f((sacc[jj][0] - m0) * CEXP);
            sacc[jj][1] = ex2f((sacc[jj][1] - m0) * CEXP);
            sacc[jj][2] = ex2f((sacc[jj][2] - m1) * CEXP);
            sacc[jj][3] = ex2f((sacc[jj][3] - m1) * CEXP);
        }

        #pragma unroll
        for (int n = 0; n < 16; ++n) {
            oacc[n][0] *= a0; oacc[n][1] *= a0;
            oacc[n][2] *= a1; oacc[n][3] *= a1;
        }
        lacc[0] *= a0; lacc[1] *= a0;
        lacc[2] *= a1; lacc[3] *= a1;

        #pragma unroll
        for (int kc2 = 0; kc2 < 8; ++kc2) {
            uint32_t ap[4];
            ap[0] = pkh(__float2half_rn(sacc[2 * kc2][0]),
                        __float2half_rn(sacc[2 * kc2][1]));
            ap[1] = pkh(__float2half_rn(sacc[2 * kc2][2]),
                        __float2half_rn(sacc[2 * kc2][3]));
            ap[2] = pkh(__float2half_rn(sacc[2 * kc2 + 1][0]),
                        __float2half_rn(sacc[2 * kc2 + 1][1]));
            ap[3] = pkh(__float2half_rn(sacc[2 * kc2 + 1][2]),
                        __float2half_rn(sacc[2 * kc2 + 1][3]));
            const int c16 = 2 * kc2 + bcsel;
            uint32_t bf[2][4];
            ldsm4(bf[0], vb + (c16 >> 3) * 16384 + swz(brow_base, c16 & 7));
            #pragma unroll
            for (int nn2 = 0; nn2 < 8; ++nn2) {
                const int cur = nn2 & 1, nxt = cur ^ 1;
                if (nn2 + 1 < 8) {
                    const int row = 16 * (nn2 + 1) + brow_base;
                    ldsm4(bf[nxt], vb + (c16 >> 3) * 16384 + swz(row, c16 & 7));
                }
                mma_f16(oacc[2 * nn2],     ap, bf[cur]);
                mma_f16(oacc[2 * nn2 + 1], ap, bf[cur] + 2);
            }
            mma_f16(lacc, ap, bones);         // row sums via tensor core
        }
        __syncthreads();
    }

    const float i0 = 1.f / lacc[0];
    const float i1 = 1.f / lacc[2];
    const int r0g = q0 + wr + (lane >> 2);
    f16* o0 = Og + (size_t)(b * kS + r0g) * kH + h * kHD;
    f16* o1 = Og + (size_t)(b * kS + r0g + 8) * kH + h * kHD;
    #pragma unroll
    for (int nb = 0; nb < 16; ++nb) {
        const int col = 8 * nb + 2 * (lane & 3);
        *reinterpret_cast<uint32_t*>(o0 + col) =
            pkh(__float2half_rn(oacc[nb][0] * i0),
                __float2half_rn(oacc[nb][1] * i0));
        *reinterpret_cast<uint32_t*>(o1 + col) =
            pkh(__float2half_rn(oacc[nb][2] * i1),
                __float2half_rn(oacc[nb][3] * i1));
    }
}

// ---------------------------------------------------------------------------
extern "C" void kernel_launch(void* const* d_in, const int* in_sizes, int n_in,
                              void* d_out, int out_size)
{
    const float* hs = (const float*)d_in[0];
    // d_in[1] = attention_mask (causal; applied analytically)
    const float* W[4] = {(const float*)d_in[2], (const float*)d_in[3],
                         (const float*)d_in[4], (const float*)d_in[5]};
    float* out = (float*)d_out;

    f16 *hh, *wh, *qh, *kh, *vth, *aoh;
    cudaGetSymbolAddress((void**)&hh,  g_hh);
    cudaGetSymbolAddress((void**)&wh,  g_wh);
    cudaGetSymbolAddress((void**)&qh,  g_qh);
    cudaGetSymbolAddress((void**)&kh,  g_kh);
    cudaGetSymbolAddress((void**)&vth, g_vth);
    cudaGetSymbolAddress((void**)&aoh, g_aoh);

    cudaFuncSetAttribute(mm_qkv, cudaFuncAttributeMaxDynamicSharedMemorySize, SMEM_G);
    cudaFuncSetAttribute(mm_o,   cudaFuncAttributeMaxDynamicSharedMemorySize, SMEM_G);
    cudaFuncSetAttribute(fattn_k, cudaFuncAttributeMaxDynamicSharedMemorySize, ATT_SMEM);

    const size_t WN = (size_t)kH * kH;

    // All fp32 -> fp16 conversions, one launch, 4 float4 per thread (MLP=4)
    split_all<<<2048 + 4 * 1024, 256>>>((const float4*)hs,
                                        (const float4*)W[0], (const float4*)W[1],
                                        (const float4*)W[2], (const float4*)W[3],
                                        (uint2*)hh, (uint2*)wh);

    // Fused Q,K,V projections: 48 x 64 CTAs of 128 threads (4 CTAs/SM)
    mm_qkv<<<dim3(48, kM / TMG), 128, SMEM_G>>>(hh, wh, qh, kh, vth);

    // Fused scores + softmax + PV
    fattn_k<<<dim3(kS / QT, kB * kNH), 256, ATT_SMEM>>>(qh, kh, vth, aoh);

    // Output projection: 16 x 64 CTAs
    mm_o<<<dim3(kH / TNG, kM / TMG), 128, SMEM_G>>>(aoh, wh + 3 * WN, out);
}